// round 13
// baseline (speedup 1.0000x reference)
#include <cuda_runtime.h>
#include <cuda_bf16.h>
#include <cstdint>

#define NNODES 50000
#define NEDGES 640000
#define HID    128
#define CLS    64
#define NT     391            // ceil(50000/128) M-tiles
#define NT0    196            // first-half tiles
#define NT1    (NT - NT0)     // 195
#define SPLITN (NT0 * 128)    // 25088

#define SCAN_BLK 1024
#define NSCANBLK ((NNODES + SCAN_BLK - 1) / SCAN_BLK)   // 49

typedef unsigned long long u64;

// ---------------- scratch (static __device__, no allocation) ----------------
__device__ float g_h[NNODES * HID];                        // fp32 hidden (buf A)
__device__ float g_h2[NNODES * HID];                       // fp32 hidden (agg scratch)
__device__ float g_h3[NNODES * HID];                       // fp32 hidden (buf C)
__device__ __align__(16) unsigned char g_Whi[3 * 32768 + 16384]; // W^T tiles
__device__ __align__(16) unsigned char g_Wlo[3 * 32768 + 16384];
__device__ float g_dinv[NNODES];
__device__ int   g_cnt[NNODES];      // zero-initialized; invariant restored by k_agg
__device__ int   g_rowptr[NNODES + 1];
__device__ int   g_pos[NNODES];
__device__ __align__(8) int2 g_edge[NEDGES];   // fused (srow, dinv-bits)

// ---------------- helpers ----------------
__device__ __forceinline__ uint32_t smem_to_u32(const void* p) {
    uint32_t a;
    asm("{ .reg .u64 t; cvta.to.shared.u64 t, %1; cvt.u32.u64 %0, t; }" : "=r"(a) : "l"(p));
    return a;
}

// tile layout: 128-bf16 rows (256B), 16B chunks XOR-swizzled by row
__device__ __forceinline__ uint32_t tile_off(int r, int k) {
    return (uint32_t)(r * 256 + 16 * (((k >> 3) ^ (r & 7))) + (k & 7) * 2);
}

__device__ __forceinline__ void ldsm4(uint32_t* r, uint32_t addr) {
    asm volatile("ldmatrix.sync.aligned.m8n8.x4.shared.b16 {%0,%1,%2,%3}, [%4];"
                 : "=r"(r[0]), "=r"(r[1]), "=r"(r[2]), "=r"(r[3]) : "r"(addr));
}
__device__ __forceinline__ void mma16816(float* c, const uint32_t* a, const uint32_t* b) {
    asm volatile("mma.sync.aligned.m16n8k16.row.col.f32.bf16.bf16.f32 "
                 "{%0,%1,%2,%3}, {%4,%5,%6,%7}, {%8,%9}, {%0,%1,%2,%3};"
                 : "+f"(c[0]), "+f"(c[1]), "+f"(c[2]), "+f"(c[3])
                 : "r"(a[0]), "r"(a[1]), "r"(a[2]), "r"(a[3]), "r"(b[0]), "r"(b[1]));
}

// split one float4 into hi/lo bf16x4 and store 8B each
__device__ __forceinline__ void split_store(char* hiB, char* loB, uint32_t off, float4 v) {
    __nv_bfloat162 h0 = __floats2bfloat162_rn(v.x, v.y);
    __nv_bfloat162 h1 = __floats2bfloat162_rn(v.z, v.w);
    float rx = v.x - __low2float(h0);
    float ry = v.y - __high2float(h0);
    float rz = v.z - __low2float(h1);
    float rw = v.w - __high2float(h1);
    __nv_bfloat162 l0 = __floats2bfloat162_rn(rx, ry);
    __nv_bfloat162 l1 = __floats2bfloat162_rn(rz, rw);
    uint2 hu = make_uint2(*(uint32_t*)&h0, *(uint32_t*)&h1);
    uint2 lu = make_uint2(*(uint32_t*)&l0, *(uint32_t*)&l1);
    *reinterpret_cast<uint2*>(hiB + off) = hu;
    *reinterpret_cast<uint2*>(loB + off) = lu;
}

// ---------------- preprocessing ----------------
__global__ void k_count(const int* __restrict__ col) {
    int e = blockIdx.x * blockDim.x + threadIdx.x;
    if (e < NEDGES) atomicAdd(&g_cnt[col[e]], 1);
}

// fused: per-block prefix base + dinv + scan -> rowptr/pos (g_cnt cleared in k_agg)
__global__ void k_scan_fused() {
    __shared__ int warp_sums[32];
    __shared__ int s_base;
    const int tid  = threadIdx.x;
    const int lane = tid & 31;
    const int wid  = tid >> 5;
    const int bid  = blockIdx.x;

    int pre = 0;
    const int lim = bid * SCAN_BLK;
    for (int j = tid; j < lim; j += SCAN_BLK) pre += g_cnt[j];
    #pragma unroll
    for (int o = 16; o > 0; o >>= 1) pre += __shfl_down_sync(0xffffffffu, pre, o);
    if (lane == 0) warp_sums[wid] = pre;
    __syncthreads();
    if (wid == 0) {
        int s = warp_sums[lane];
        #pragma unroll
        for (int o = 16; o > 0; o >>= 1) s += __shfl_down_sync(0xffffffffu, s, o);
        if (lane == 0) s_base = s;
    }
    __syncthreads();

    if (bid == 0 && tid == 0) g_rowptr[NNODES] = NEDGES;

    int i = bid * SCAN_BLK + tid;
    int v = 0;
    if (i < NNODES) {
        v = g_cnt[i];
        g_dinv[i] = rsqrtf((float)v + 1.0f);
    }
    int x = v;
    #pragma unroll
    for (int o = 1; o < 32; o <<= 1) {
        int y = __shfl_up_sync(0xffffffffu, x, o);
        if (lane >= o) x += y;
    }
    if (lane == 31) warp_sums[wid] = x;
    __syncthreads();
    if (wid == 0) {
        int s = warp_sums[lane];
        #pragma unroll
        for (int o = 1; o < 32; o <<= 1) {
            int y = __shfl_up_sync(0xffffffffu, s, o);
            if (lane >= o) s += y;
        }
        warp_sums[lane] = s;
    }
    __syncthreads();
    int excl = s_base + x - v + (wid > 0 ? warp_sums[wid - 1] : 0);
    if (i < NNODES) { g_rowptr[i] = excl; g_pos[i] = excl; }
}

__global__ void k_scatter(const int* __restrict__ row, const int* __restrict__ col) {
    int e = blockIdx.x * blockDim.x + threadIdx.x;
    if (e < NEDGES) {
        int c = col[e];
        int r = row[e];
        int p = atomicAdd(&g_pos[c], 1);
        g_edge[p] = make_int2(r, __float_as_int(g_dinv[r]));
    }
}

// ---------------- weight prep: W[K,N] -> W^T[N,K] tiles, hi/lo ----------------
__global__ void k_wprep(const float* __restrict__ W0, const float* __restrict__ W1,
                        const float* __restrict__ W2, const float* __restrict__ Wlin) {
    int idx = blockIdx.x * blockDim.x + threadIdx.x;
    if (idx >= 3 * 16384 + 8192) return;
    float w;
    uint32_t dst;
    if (idx < 3 * 16384) {
        int g = idx >> 14;
        int rem = idx & 16383;
        int k = rem >> 7;
        int n = rem & 127;
        const float* W = (g == 0) ? W0 : (g == 1) ? W1 : W2;
        w = W[k * 128 + n];
        dst = g * 32768 + tile_off(n, k);
    } else {
        int rem = idx - 3 * 16384;
        int k = rem >> 6;
        int n = rem & 63;
        w = Wlin[k * 64 + n];
        dst = 3 * 32768 + tile_off(n, k);
    }
    __nv_bfloat16 hi = __float2bfloat16_rn(w);
    float lo = w - __bfloat162float(hi);
    *reinterpret_cast<__nv_bfloat16*>(g_Whi + dst) = hi;
    *reinterpret_cast<__nv_bfloat16*>(g_Wlo + dst) = __float2bfloat16_rn(lo);
}

// ---------------- tensor-core GEMM via mma.sync, split-bf16 x3 passes ----------
// C[tileBase.., NCOLS] = A @ W; A fp32, split hi/lo into smem on load.
template <int NCOLS>
__global__ __launch_bounds__(256, 1)
void k_gemm_mma(const float* __restrict__ A,
                const uint4* __restrict__ Bhi4, const uint4* __restrict__ Blo4,
                const float* __restrict__ bias, float* __restrict__ C,
                int tileBase) {
    constexpr int A_BYTES = 32768;
    constexpr int B_BYTES = NCOLS * 256;
    constexpr int OFF_AHI = 0;
    constexpr int OFF_ALO = A_BYTES;
    constexpr int OFF_BHI = 2 * A_BYTES;
    constexpr int OFF_BLO = 2 * A_BYTES + B_BYTES;
    constexpr int NT8 = NCOLS / 16;
    extern __shared__ __align__(16) char smem[];

    const int tid  = threadIdx.x;
    const int wid  = tid >> 5;
    const int lane = tid & 31;
    const int tile = blockIdx.x + tileBase;

    {
        char* hiB = smem + OFF_AHI;
        char* loB = smem + OFF_ALO;
        #pragma unroll
        for (int it = 0; it < 16; it++) {
            int idx = tid + it * 256;
            int r   = idx >> 5;
            int c4  = (idx & 31) * 4;
            int gr  = tile * 128 + r;
            float4 v = make_float4(0.f, 0.f, 0.f, 0.f);
            if (gr < NNODES)
                v = *reinterpret_cast<const float4*>(A + (size_t)gr * HID + c4);
            split_store(hiB, loB, tile_off(r, c4), v);
        }
        uint4* bH = reinterpret_cast<uint4*>(smem + OFF_BHI);
        uint4* bL = reinterpret_cast<uint4*>(smem + OFF_BLO);
        #pragma unroll
        for (int i = tid; i < B_BYTES / 16; i += 256) { bH[i] = Bhi4[i]; bL[i] = Blo4[i]; }
    }
    __syncthreads();

    const int wm  = wid >> 1;
    const int wn  = wid & 1;
    const int m0w = wm * 32;
    const int n0w = wn * (NCOLS / 2);

    float acc[2][NT8][4];
    #pragma unroll
    for (int mi = 0; mi < 2; mi++)
        #pragma unroll
        for (int ni = 0; ni < NT8; ni++)
            #pragma unroll
            for (int q = 0; q < 4; q++) acc[mi][ni][q] = 0.0f;

    const uint32_t sb = smem_to_u32(smem);
    const int arow    = m0w + (lane & 15);
    const int asw     = arow & 7;
    const int akc_add = lane >> 4;
    const int bn      = n0w + (lane & 7) + ((lane >> 4) << 3);
    const int bsw     = bn & 7;
    const int bkc_add = (lane >> 3) & 1;

    #pragma unroll
    for (int pass = 0; pass < 3; pass++) {
        const uint32_t Ab = sb + ((pass == 2) ? OFF_ALO : OFF_AHI);
        const uint32_t Bb = sb + ((pass == 1) ? OFF_BLO : OFF_BHI);
        #pragma unroll
        for (int s = 0; s < 8; s++) {
            const int kca = 2 * s + akc_add;
            const int kcb = 2 * s + bkc_add;
            uint32_t a[2][4];
            #pragma unroll
            for (int mi = 0; mi < 2; mi++)
                ldsm4(a[mi], Ab + (uint32_t)((arow + mi * 16) * 256 + 16 * (kca ^ asw)));
            uint32_t b[NT8][2];
            #pragma unroll
            for (int nj = 0; nj < NT8 / 2; nj++) {
                uint32_t r[4];
                ldsm4(r, Bb + (uint32_t)((bn + nj * 16) * 256 + 16 * (kcb ^ bsw)));
                b[2 * nj][0] = r[0]; b[2 * nj][1] = r[1];
                b[2 * nj + 1][0] = r[2]; b[2 * nj + 1][1] = r[3];
            }
            #pragma unroll
            for (int mi = 0; mi < 2; mi++)
                #pragma unroll
                for (int ni = 0; ni < NT8; ni++)
                    mma16816(acc[mi][ni], a[mi], b[ni]);
        }
    }

    const int rbase = tile * 128 + m0w;
    #pragma unroll
    for (int mi = 0; mi < 2; mi++) {
        int r0 = rbase + mi * 16 + (lane >> 2);
        int r1 = r0 + 8;
        #pragma unroll
        for (int ni = 0; ni < NT8; ni++) {
            int c = n0w + ni * 8 + (lane & 3) * 2;
            float bx = 0.f, by = 0.f;
            if (bias) { bx = bias[c]; by = bias[c + 1]; }
            if (r0 < NNODES) {
                float2 v = make_float2(acc[mi][ni][0] + bx, acc[mi][ni][1] + by);
                *reinterpret_cast<float2*>(C + (size_t)r0 * NCOLS + c) = v;
            }
            if (r1 < NNODES) {
                float2 v = make_float2(acc[mi][ni][2] + bx, acc[mi][ni][3] + by);
                *reinterpret_cast<float2*>(C + (size_t)r1 * NCOLS + c) = v;
            }
        }
    }
}

// ---------------- aggregation (4-way edge ILP) over node range -----------------
__global__ void k_agg(const float* __restrict__ h,
                      const float* __restrict__ bias,
                      float* __restrict__ out,
                      int nodeBase, int nodeEnd) {
    int gwarp = nodeBase + ((blockIdx.x * blockDim.x + threadIdx.x) >> 5);
    int lane  = threadIdx.x & 31;
    if (gwarp >= nodeEnd) return;
    const int n = gwarp;
    if (lane == 0) g_cnt[n] = 0;     // maintain zero-invariant (idempotent)

    const float dn = g_dinv[n];
    const size_t feat = (size_t)lane * 4;

    float4 self = *reinterpret_cast<const float4*>(h + (size_t)n * HID + feat);
    const float sn = dn * dn;
    float4 acc0 = make_float4(self.x * sn, self.y * sn, self.z * sn, self.w * sn);
    float4 acc1 = make_float4(0.f, 0.f, 0.f, 0.f);
    float4 acc2 = make_float4(0.f, 0.f, 0.f, 0.f);
    float4 acc3 = make_float4(0.f, 0.f, 0.f, 0.f);

    const int beg = g_rowptr[n];
    const int end = g_rowptr[n + 1];

    int e = beg;
    for (; e + 4 <= end; e += 4) {
        int2 e0 = g_edge[e],     e1 = g_edge[e + 1];
        int2 e2 = g_edge[e + 2], e3 = g_edge[e + 3];
        float w0 = __int_as_float(e0.y) * dn, w1 = __int_as_float(e1.y) * dn;
        float w2 = __int_as_float(e2.y) * dn, w3 = __int_as_float(e3.y) * dn;
        float4 v0 = *reinterpret_cast<const float4*>(h + (size_t)e0.x * HID + feat);
        float4 v1 = *reinterpret_cast<const float4*>(h + (size_t)e1.x * HID + feat);
        float4 v2 = *reinterpret_cast<const float4*>(h + (size_t)e2.x * HID + feat);
        float4 v3 = *reinterpret_cast<const float4*>(h + (size_t)e3.x * HID + feat);
        acc0.x += v0.x * w0; acc0.y += v0.y * w0; acc0.z += v0.z * w0; acc0.w += v0.w * w0;
        acc1.x += v1.x * w1; acc1.y += v1.y * w1; acc1.z += v1.z * w1; acc1.w += v1.w * w1;
        acc2.x += v2.x * w2; acc2.y += v2.y * w2; acc2.z += v2.z * w2; acc2.w += v2.w * w2;
        acc3.x += v3.x * w3; acc3.y += v3.y * w3; acc3.z += v3.z * w3; acc3.w += v3.w * w3;
    }
    for (; e < end; ++e) {
        int2 ed = g_edge[e];
        float w = __int_as_float(ed.y) * dn;
        float4 v = *reinterpret_cast<const float4*>(h + (size_t)ed.x * HID + feat);
        acc0.x += v.x * w; acc0.y += v.y * w; acc0.z += v.z * w; acc0.w += v.w * w;
    }

    float4 acc;
    acc.x = (acc0.x + acc1.x) + (acc2.x + acc3.x);
    acc.y = (acc0.y + acc1.y) + (acc2.y + acc3.y);
    acc.z = (acc0.z + acc1.z) + (acc2.z + acc3.z);
    acc.w = (acc0.w + acc1.w) + (acc2.w + acc3.w);

    float4 b = *reinterpret_cast<const float4*>(bias + feat);
    acc.x = fmaxf(acc.x + b.x, 0.0f);
    acc.y = fmaxf(acc.y + b.y, 0.0f);
    acc.z = fmaxf(acc.z + b.z, 0.0f);
    acc.w = fmaxf(acc.w + b.w, 0.0f);

    *reinterpret_cast<float4*>(out + (size_t)n * HID + feat) = acc;
}

// ---------------- launch ----------------
extern "C" void kernel_launch(void* const* d_in, const int* in_sizes, int n_in,
                              void* d_out, int out_size) {
    const float* x    = (const float*)d_in[0];
    const int*   ei   = (const int*)d_in[1];
    const int*   row  = ei;
    const int*   col  = ei + NEDGES;
    const float* W0   = (const float*)d_in[2];
    const float* b0   = (const float*)d_in[3];
    const float* W1   = (const float*)d_in[4];
    const float* b1   = (const float*)d_in[5];
    const float* W2   = (const float*)d_in[6];
    const float* b2   = (const float*)d_in[7];
    const float* Wlin = (const float*)d_in[8];
    const float* blin = (const float*)d_in[9];
    float* out = (float*)d_out;

    float *hA, *hS, *hC;
    cudaGetSymbolAddress((void**)&hA, g_h);    // buf A
    cudaGetSymbolAddress((void**)&hS, g_h2);   // agg scratch
    cudaGetSymbolAddress((void**)&hC, g_h3);   // buf C
    unsigned char *whi, *wlo;
    cudaGetSymbolAddress((void**)&whi, g_Whi);
    cudaGetSymbolAddress((void**)&wlo, g_Wlo);

    constexpr int SMEM_128 = 2 * 32768 + 2 * 32768;  // 131072
    constexpr int SMEM_64  = 2 * 32768 + 2 * 16384;  //  98304
    cudaFuncSetAttribute(k_gemm_mma<128>, cudaFuncAttributeMaxDynamicSharedMemorySize, SMEM_128);
    cudaFuncSetAttribute(k_gemm_mma<64>,  cudaFuncAttributeMaxDynamicSharedMemorySize, SMEM_64);

    // one-time side-stream + events (handles only; no device memory)
    static cudaStream_t s2 = nullptr;
    static cudaEvent_t evFork = nullptr, evJoin = nullptr;
    static cudaEvent_t eA[3], eG[3];
    if (s2 == nullptr) {
        cudaStreamCreateWithFlags(&s2, cudaStreamNonBlocking);
        cudaEventCreateWithFlags(&evFork, cudaEventDisableTiming);
        cudaEventCreateWithFlags(&evJoin, cudaEventDisableTiming);
        for (int i = 0; i < 3; i++) {
            cudaEventCreateWithFlags(&eA[i], cudaEventDisableTiming);
            cudaEventCreateWithFlags(&eG[i], cudaEventDisableTiming);
        }
    }

    // fork: weight prep + layer-0 GEMM (independent of graph) on s2 -> z0 in hA
    cudaEventRecord(evFork, 0);
    cudaStreamWaitEvent(s2, evFork, 0);
    k_wprep<<<(3 * 16384 + 8192 + 255) / 256, 256, 0, s2>>>(W0, W1, W2, Wlin);
    k_gemm_mma<128><<<NT, 256, SMEM_128, s2>>>(x, (const uint4*)(whi + 0 * 32768),
                                               (const uint4*)(wlo + 0 * 32768), nullptr, hA, 0);
    cudaEventRecord(evJoin, s2);

    // main stream: graph preprocessing
    k_count<<<(NEDGES + 255) / 256, 256>>>(col);
    k_scan_fused<<<NSCANBLK, SCAN_BLK>>>();
    k_scatter<<<(NEDGES + 255) / 256, 256>>>(row, col);

    // join
    cudaStreamWaitEvent(0, evJoin, 0);

    const int aggBlk0 = (SPLITN * 32) / 256;                       // 3136
    const int aggBlk1 = ((NNODES - SPLITN) * 32 + 255) / 256;      // 3114

    // boundary 0: agg(hA)+b0 -> hS ; gemm W1(hS) -> hC
    k_agg<<<aggBlk0, 256>>>(hA, b0, hS, 0, SPLITN);
    cudaEventRecord(eA[0], 0);
    cudaStreamWaitEvent(s2, eA[0], 0);
    k_gemm_mma<128><<<NT0, 256, SMEM_128, s2>>>(hS, (const uint4*)(whi + 1 * 32768),
                                                (const uint4*)(wlo + 1 * 32768), nullptr, hC, 0);
    cudaEventRecord(eG[0], s2);
    k_agg<<<aggBlk1, 256>>>(hA, b0, hS, SPLITN, NNODES);
    k_gemm_mma<128><<<NT1, 256, SMEM_128>>>(hS, (const uint4*)(whi + 1 * 32768),
                                            (const uint4*)(wlo + 1 * 32768), nullptr, hC, NT0);
    cudaStreamWaitEvent(0, eG[0], 0);

    // boundary 1: agg(hC)+b1 -> hS ; gemm W2(hS) -> hA
    k_agg<<<aggBlk0, 256>>>(hC, b1, hS, 0, SPLITN);
    cudaEventRecord(eA[1], 0);
    cudaStreamWaitEvent(s2, eA[1], 0);
    k_gemm_mma<128><<<NT0, 256, SMEM_128, s2>>>(hS, (const uint4*)(whi + 2 * 32768),
                                                (const uint4*)(wlo + 2 * 32768), nullptr, hA, 0);
    cudaEventRecord(eG[1], s2);
    k_agg<<<aggBlk1, 256>>>(hC, b1, hS, SPLITN, NNODES);
    k_gemm_mma<128><<<NT1, 256, SMEM_128>>>(hS, (const uint4*)(whi + 2 * 32768),
                                            (const uint4*)(wlo + 2 * 32768), nullptr, hA, NT0);
    cudaStreamWaitEvent(0, eG[1], 0);

    // boundary 2: agg(hA)+b2 -> hS ; head gemm Wlin(hS) + blin -> out
    k_agg<<<aggBlk0, 256>>>(hA, b2, hS, 0, SPLITN);
    cudaEventRecord(eA[2], 0);
    cudaStreamWaitEvent(s2, eA[2], 0);
    k_gemm_mma<64><<<NT0, 256, SMEM_64, s2>>>(hS, (const uint4*)(whi + 3 * 32768),
                                              (const uint4*)(wlo + 3 * 32768), blin, out, 0);
    cudaEventRecord(eG[2], s2);
    k_agg<<<aggBlk1, 256>>>(hA, b2, hS, SPLITN, NNODES);
    k_gemm_mma<64><<<NT1, 256, SMEM_64>>>(hS, (const uint4*)(whi + 3 * 32768),
                                          (const uint4*)(wlo + 3 * 32768), blin, out, NT0);
    cudaStreamWaitEvent(0, eG[2], 0);
}

// round 14
// speedup vs baseline: 1.0455x; 1.0455x over previous
#include <cuda_runtime.h>
#include <cuda_bf16.h>
#include <cstdint>

#define NNODES 50000
#define NEDGES 640000
#define HID    128
#define CLS    64
#define NT     391            // ceil(50000/128) M-tiles

#define SCAN_BLK 1024
#define NSCANBLK ((NNODES + SCAN_BLK - 1) / SCAN_BLK)   // 49

typedef unsigned long long u64;

// ---------------- scratch (static __device__, no allocation) ----------------
__device__ float g_h[NNODES * HID];                        // fp32 hidden (ping)
__device__ float g_h2[NNODES * HID];                       // fp32 hidden (pong)
__device__ __align__(16) unsigned char g_Whi[3 * 32768 + 16384]; // W^T tiles
__device__ __align__(16) unsigned char g_Wlo[3 * 32768 + 16384];
__device__ float g_dinv[NNODES];
__device__ int   g_cnt[NNODES];      // zero-initialized; invariant restored by k_agg
__device__ int   g_rowptr[NNODES + 1];
__device__ int   g_pos[NNODES];
__device__ __align__(8) int2 g_edge[NEDGES];   // fused (srow, dinv-bits)

// ---------------- helpers ----------------
__device__ __forceinline__ uint32_t smem_to_u32(const void* p) {
    uint32_t a;
    asm("{ .reg .u64 t; cvta.to.shared.u64 t, %1; cvt.u32.u64 %0, t; }" : "=r"(a) : "l"(p));
    return a;
}

// tile layout: 128-bf16 rows (256B), 16B chunks XOR-swizzled by row
__device__ __forceinline__ uint32_t tile_off(int r, int k) {
    return (uint32_t)(r * 256 + 16 * (((k >> 3) ^ (r & 7))) + (k & 7) * 2);
}

__device__ __forceinline__ void ldsm4(uint32_t* r, uint32_t addr) {
    asm volatile("ldmatrix.sync.aligned.m8n8.x4.shared.b16 {%0,%1,%2,%3}, [%4];"
                 : "=r"(r[0]), "=r"(r[1]), "=r"(r[2]), "=r"(r[3]) : "r"(addr));
}
__device__ __forceinline__ void mma16816(float* c, const uint32_t* a, const uint32_t* b) {
    asm volatile("mma.sync.aligned.m16n8k16.row.col.f32.bf16.bf16.f32 "
                 "{%0,%1,%2,%3}, {%4,%5,%6,%7}, {%8,%9}, {%0,%1,%2,%3};"
                 : "+f"(c[0]), "+f"(c[1]), "+f"(c[2]), "+f"(c[3])
                 : "r"(a[0]), "r"(a[1]), "r"(a[2]), "r"(a[3]), "r"(b[0]), "r"(b[1]));
}

// split one float4 into hi/lo bf16x4 and store 8B each
__device__ __forceinline__ void split_store(char* hiB, char* loB, uint32_t off, float4 v) {
    __nv_bfloat162 h0 = __floats2bfloat162_rn(v.x, v.y);
    __nv_bfloat162 h1 = __floats2bfloat162_rn(v.z, v.w);
    float rx = v.x - __low2float(h0);
    float ry = v.y - __high2float(h0);
    float rz = v.z - __low2float(h1);
    float rw = v.w - __high2float(h1);
    __nv_bfloat162 l0 = __floats2bfloat162_rn(rx, ry);
    __nv_bfloat162 l1 = __floats2bfloat162_rn(rz, rw);
    uint2 hu = make_uint2(*(uint32_t*)&h0, *(uint32_t*)&h1);
    uint2 lu = make_uint2(*(uint32_t*)&l0, *(uint32_t*)&l1);
    *reinterpret_cast<uint2*>(hiB + off) = hu;
    *reinterpret_cast<uint2*>(loB + off) = lu;
}

// ---------------- preprocessing ----------------
__global__ void k_count(const int* __restrict__ col) {
    int e = blockIdx.x * blockDim.x + threadIdx.x;
    if (e < NEDGES) atomicAdd(&g_cnt[col[e]], 1);
}

// fused: per-block prefix base + dinv + scan -> rowptr/pos (g_cnt cleared in k_agg)
__global__ void k_scan_fused() {
    __shared__ int warp_sums[32];
    __shared__ int s_base;
    const int tid  = threadIdx.x;
    const int lane = tid & 31;
    const int wid  = tid >> 5;
    const int bid  = blockIdx.x;

    int pre = 0;
    const int lim = bid * SCAN_BLK;
    for (int j = tid; j < lim; j += SCAN_BLK) pre += g_cnt[j];
    #pragma unroll
    for (int o = 16; o > 0; o >>= 1) pre += __shfl_down_sync(0xffffffffu, pre, o);
    if (lane == 0) warp_sums[wid] = pre;
    __syncthreads();
    if (wid == 0) {
        int s = warp_sums[lane];
        #pragma unroll
        for (int o = 16; o > 0; o >>= 1) s += __shfl_down_sync(0xffffffffu, s, o);
        if (lane == 0) s_base = s;
    }
    __syncthreads();

    if (bid == 0 && tid == 0) g_rowptr[NNODES] = NEDGES;

    int i = bid * SCAN_BLK + tid;
    int v = 0;
    if (i < NNODES) {
        v = g_cnt[i];
        g_dinv[i] = rsqrtf((float)v + 1.0f);
    }
    int x = v;
    #pragma unroll
    for (int o = 1; o < 32; o <<= 1) {
        int y = __shfl_up_sync(0xffffffffu, x, o);
        if (lane >= o) x += y;
    }
    if (lane == 31) warp_sums[wid] = x;
    __syncthreads();
    if (wid == 0) {
        int s = warp_sums[lane];
        #pragma unroll
        for (int o = 1; o < 32; o <<= 1) {
            int y = __shfl_up_sync(0xffffffffu, s, o);
            if (lane >= o) s += y;
        }
        warp_sums[lane] = s;
    }
    __syncthreads();
    int excl = s_base + x - v + (wid > 0 ? warp_sums[wid - 1] : 0);
    if (i < NNODES) { g_rowptr[i] = excl; g_pos[i] = excl; }
}

__global__ void k_scatter(const int* __restrict__ row, const int* __restrict__ col) {
    int e = blockIdx.x * blockDim.x + threadIdx.x;
    if (e < NEDGES) {
        int c = col[e];
        int r = row[e];
        int p = atomicAdd(&g_pos[c], 1);
        g_edge[p] = make_int2(r, __float_as_int(g_dinv[r]));
    }
}

// ---------------- weight prep: W[K,N] -> W^T[N,K] tiles, hi/lo ----------------
__global__ void k_wprep(const float* __restrict__ W0, const float* __restrict__ W1,
                        const float* __restrict__ W2, const float* __restrict__ Wlin) {
    int idx = blockIdx.x * blockDim.x + threadIdx.x;
    if (idx >= 3 * 16384 + 8192) return;
    float w;
    uint32_t dst;
    if (idx < 3 * 16384) {
        int g = idx >> 14;
        int rem = idx & 16383;
        int k = rem >> 7;
        int n = rem & 127;
        const float* W = (g == 0) ? W0 : (g == 1) ? W1 : W2;
        w = W[k * 128 + n];
        dst = g * 32768 + tile_off(n, k);
    } else {
        int rem = idx - 3 * 16384;
        int k = rem >> 6;
        int n = rem & 63;
        w = Wlin[k * 64 + n];
        dst = 3 * 32768 + tile_off(n, k);
    }
    __nv_bfloat16 hi = __float2bfloat16_rn(w);
    float lo = w - __bfloat162float(hi);
    *reinterpret_cast<__nv_bfloat16*>(g_Whi + dst) = hi;
    *reinterpret_cast<__nv_bfloat16*>(g_Wlo + dst) = __float2bfloat16_rn(lo);
}

// ---------------- tensor-core GEMM via mma.sync, split-bf16 x3 passes ----------
// C[M, NCOLS] = A[M,128] @ W[128,NCOLS]; A fp32, split hi/lo into smem on load.
template <int NCOLS>
__global__ __launch_bounds__(256, 1)
void k_gemm_mma(const float* __restrict__ A,
                const uint4* __restrict__ Bhi4, const uint4* __restrict__ Blo4,
                const float* __restrict__ bias, float* __restrict__ C) {
    constexpr int A_BYTES = 32768;
    constexpr int B_BYTES = NCOLS * 256;
    constexpr int OFF_AHI = 0;
    constexpr int OFF_ALO = A_BYTES;
    constexpr int OFF_BHI = 2 * A_BYTES;
    constexpr int OFF_BLO = 2 * A_BYTES + B_BYTES;
    constexpr int NT8 = NCOLS / 16;
    extern __shared__ __align__(16) char smem[];

    const int tid  = threadIdx.x;
    const int wid  = tid >> 5;
    const int lane = tid & 31;
    const int tile = blockIdx.x;

    {
        char* hiB = smem + OFF_AHI;
        char* loB = smem + OFF_ALO;
        #pragma unroll
        for (int it = 0; it < 16; it++) {
            int idx = tid + it * 256;
            int r   = idx >> 5;
            int c4  = (idx & 31) * 4;
            int gr  = tile * 128 + r;
            float4 v = make_float4(0.f, 0.f, 0.f, 0.f);
            if (gr < NNODES)
                v = *reinterpret_cast<const float4*>(A + (size_t)gr * HID + c4);
            split_store(hiB, loB, tile_off(r, c4), v);
        }
        uint4* bH = reinterpret_cast<uint4*>(smem + OFF_BHI);
        uint4* bL = reinterpret_cast<uint4*>(smem + OFF_BLO);
        #pragma unroll
        for (int i = tid; i < B_BYTES / 16; i += 256) { bH[i] = Bhi4[i]; bL[i] = Blo4[i]; }
    }
    __syncthreads();

    const int wm  = wid >> 1;
    const int wn  = wid & 1;
    const int m0w = wm * 32;
    const int n0w = wn * (NCOLS / 2);

    float acc[2][NT8][4];
    #pragma unroll
    for (int mi = 0; mi < 2; mi++)
        #pragma unroll
        for (int ni = 0; ni < NT8; ni++)
            #pragma unroll
            for (int q = 0; q < 4; q++) acc[mi][ni][q] = 0.0f;

    const uint32_t sb = smem_to_u32(smem);
    const int arow    = m0w + (lane & 15);
    const int asw     = arow & 7;
    const int akc_add = lane >> 4;
    const int bn      = n0w + (lane & 7) + ((lane >> 4) << 3);
    const int bsw     = bn & 7;
    const int bkc_add = (lane >> 3) & 1;

    #pragma unroll
    for (int pass = 0; pass < 3; pass++) {
        const uint32_t Ab = sb + ((pass == 2) ? OFF_ALO : OFF_AHI);
        const uint32_t Bb = sb + ((pass == 1) ? OFF_BLO : OFF_BHI);
        #pragma unroll
        for (int s = 0; s < 8; s++) {
            const int kca = 2 * s + akc_add;
            const int kcb = 2 * s + bkc_add;
            uint32_t a[2][4];
            #pragma unroll
            for (int mi = 0; mi < 2; mi++)
                ldsm4(a[mi], Ab + (uint32_t)((arow + mi * 16) * 256 + 16 * (kca ^ asw)));
            uint32_t b[NT8][2];
            #pragma unroll
            for (int nj = 0; nj < NT8 / 2; nj++) {
                uint32_t r[4];
                ldsm4(r, Bb + (uint32_t)((bn + nj * 16) * 256 + 16 * (kcb ^ bsw)));
                b[2 * nj][0] = r[0]; b[2 * nj][1] = r[1];
                b[2 * nj + 1][0] = r[2]; b[2 * nj + 1][1] = r[3];
            }
            #pragma unroll
            for (int mi = 0; mi < 2; mi++)
                #pragma unroll
                for (int ni = 0; ni < NT8; ni++)
                    mma16816(acc[mi][ni], a[mi], b[ni]);
        }
    }

    const int rbase = tile * 128 + m0w;
    #pragma unroll
    for (int mi = 0; mi < 2; mi++) {
        int r0 = rbase + mi * 16 + (lane >> 2);
        int r1 = r0 + 8;
        #pragma unroll
        for (int ni = 0; ni < NT8; ni++) {
            int c = n0w + ni * 8 + (lane & 3) * 2;
            float bx = 0.f, by = 0.f;
            if (bias) { bx = bias[c]; by = bias[c + 1]; }
            if (r0 < NNODES) {
                float2 v = make_float2(acc[mi][ni][0] + bx, acc[mi][ni][1] + by);
                *reinterpret_cast<float2*>(C + (size_t)r0 * NCOLS + c) = v;
            }
            if (r1 < NNODES) {
                float2 v = make_float2(acc[mi][ni][2] + bx, acc[mi][ni][3] + by);
                *reinterpret_cast<float2*>(C + (size_t)r1 * NCOLS + c) = v;
            }
        }
    }
}

// ---------------- aggregation (4-way edge ILP): fp32 in, fp32 out ----------------
// also restores the g_cnt == 0 invariant for the next launch replay
__global__ __launch_bounds__(512)
void k_agg(const float* __restrict__ h,
           const float* __restrict__ bias,
           float* __restrict__ out) {
    int gwarp = (blockIdx.x * blockDim.x + threadIdx.x) >> 5;
    int lane  = threadIdx.x & 31;
    if (gwarp >= NNODES) return;
    const int n = gwarp;
    if (lane == 0) g_cnt[n] = 0;     // maintain zero-invariant (idempotent)

    const float dn = g_dinv[n];
    const size_t feat = (size_t)lane * 4;

    float4 self = *reinterpret_cast<const float4*>(h + (size_t)n * HID + feat);
    const float sn = dn * dn;
    float4 acc0 = make_float4(self.x * sn, self.y * sn, self.z * sn, self.w * sn);
    float4 acc1 = make_float4(0.f, 0.f, 0.f, 0.f);
    float4 acc2 = make_float4(0.f, 0.f, 0.f, 0.f);
    float4 acc3 = make_float4(0.f, 0.f, 0.f, 0.f);

    const int beg = g_rowptr[n];
    const int end = g_rowptr[n + 1];

    int e = beg;
    for (; e + 4 <= end; e += 4) {
        int2 e0 = g_edge[e],     e1 = g_edge[e + 1];
        int2 e2 = g_edge[e + 2], e3 = g_edge[e + 3];
        float w0 = __int_as_float(e0.y) * dn, w1 = __int_as_float(e1.y) * dn;
        float w2 = __int_as_float(e2.y) * dn, w3 = __int_as_float(e3.y) * dn;
        float4 v0 = *reinterpret_cast<const float4*>(h + (size_t)e0.x * HID + feat);
        float4 v1 = *reinterpret_cast<const float4*>(h + (size_t)e1.x * HID + feat);
        float4 v2 = *reinterpret_cast<const float4*>(h + (size_t)e2.x * HID + feat);
        float4 v3 = *reinterpret_cast<const float4*>(h + (size_t)e3.x * HID + feat);
        acc0.x += v0.x * w0; acc0.y += v0.y * w0; acc0.z += v0.z * w0; acc0.w += v0.w * w0;
        acc1.x += v1.x * w1; acc1.y += v1.y * w1; acc1.z += v1.z * w1; acc1.w += v1.w * w1;
        acc2.x += v2.x * w2; acc2.y += v2.y * w2; acc2.z += v2.z * w2; acc2.w += v2.w * w2;
        acc3.x += v3.x * w3; acc3.y += v3.y * w3; acc3.z += v3.z * w3; acc3.w += v3.w * w3;
    }
    for (; e < end; ++e) {
        int2 ed = g_edge[e];
        float w = __int_as_float(ed.y) * dn;
        float4 v = *reinterpret_cast<const float4*>(h + (size_t)ed.x * HID + feat);
        acc0.x += v.x * w; acc0.y += v.y * w; acc0.z += v.z * w; acc0.w += v.w * w;
    }

    float4 acc;
    acc.x = (acc0.x + acc1.x) + (acc2.x + acc3.x);
    acc.y = (acc0.y + acc1.y) + (acc2.y + acc3.y);
    acc.z = (acc0.z + acc1.z) + (acc2.z + acc3.z);
    acc.w = (acc0.w + acc1.w) + (acc2.w + acc3.w);

    float4 b = *reinterpret_cast<const float4*>(bias + feat);
    acc.x = fmaxf(acc.x + b.x, 0.0f);
    acc.y = fmaxf(acc.y + b.y, 0.0f);
    acc.z = fmaxf(acc.z + b.z, 0.0f);
    acc.w = fmaxf(acc.w + b.w, 0.0f);

    *reinterpret_cast<float4*>(out + (size_t)n * HID + feat) = acc;
}

// ---------------- launch ----------------
extern "C" void kernel_launch(void* const* d_in, const int* in_sizes, int n_in,
                              void* d_out, int out_size) {
    const float* x    = (const float*)d_in[0];
    const int*   ei   = (const int*)d_in[1];
    const int*   row  = ei;
    const int*   col  = ei + NEDGES;
    const float* W0   = (const float*)d_in[2];
    const float* b0   = (const float*)d_in[3];
    const float* W1   = (const float*)d_in[4];
    const float* b1   = (const float*)d_in[5];
    const float* W2   = (const float*)d_in[6];
    const float* b2   = (const float*)d_in[7];
    const float* Wlin = (const float*)d_in[8];
    const float* blin = (const float*)d_in[9];
    float* out = (float*)d_out;

    float *hPtr, *h2Ptr;
    cudaGetSymbolAddress((void**)&hPtr, g_h);
    cudaGetSymbolAddress((void**)&h2Ptr, g_h2);
    unsigned char *whi, *wlo;
    cudaGetSymbolAddress((void**)&whi, g_Whi);
    cudaGetSymbolAddress((void**)&wlo, g_Wlo);

    constexpr int SMEM_128 = 2 * 32768 + 2 * 32768;  // 131072
    constexpr int SMEM_64  = 2 * 32768 + 2 * 16384;  //  98304
    cudaFuncSetAttribute(k_gemm_mma<128>, cudaFuncAttributeMaxDynamicSharedMemorySize, SMEM_128);
    cudaFuncSetAttribute(k_gemm_mma<64>,  cudaFuncAttributeMaxDynamicSharedMemorySize, SMEM_64);

    // one-time side-stream + events (handles only; no device memory)
    static cudaStream_t s2 = nullptr;
    static cudaEvent_t evFork = nullptr, evJoin = nullptr;
    if (s2 == nullptr) {
        cudaStreamCreateWithFlags(&s2, cudaStreamNonBlocking);
        cudaEventCreateWithFlags(&evFork, cudaEventDisableTiming);
        cudaEventCreateWithFlags(&evJoin, cudaEventDisableTiming);
    }

    // fork: weight prep + layer-0 GEMM (independent of graph) on s2
    cudaEventRecord(evFork, 0);
    cudaStreamWaitEvent(s2, evFork, 0);
    k_wprep<<<(3 * 16384 + 8192 + 255) / 256, 256, 0, s2>>>(W0, W1, W2, Wlin);
    k_gemm_mma<128><<<NT, 256, SMEM_128, s2>>>(x, (const uint4*)(whi + 0 * 32768),
                                               (const uint4*)(wlo + 0 * 32768), nullptr, hPtr);
    cudaEventRecord(evJoin, s2);

    // main stream: graph preprocessing (g_cnt zero-invariant restored by k_agg)
    k_count<<<(NEDGES + 255) / 256, 256>>>(col);
    k_scan_fused<<<NSCANBLK, SCAN_BLK>>>();
    k_scatter<<<(NEDGES + 255) / 256, 256>>>(row, col);

    // join
    cudaStreamWaitEvent(0, evJoin, 0);

    const int agg_blocks = (NNODES * 32 + 511) / 512;

    k_agg<<<agg_blocks, 512>>>(hPtr, b0, h2Ptr);
    // layer 1
    k_gemm_mma<128><<<NT, 256, SMEM_128>>>(h2Ptr, (const uint4*)(whi + 1 * 32768),
                                           (const uint4*)(wlo + 1 * 32768), nullptr, hPtr);
    k_agg<<<agg_blocks, 512>>>(hPtr, b1, h2Ptr);
    // layer 2
    k_gemm_mma<128><<<NT, 256, SMEM_128>>>(h2Ptr, (const uint4*)(whi + 2 * 32768),
                                           (const uint4*)(wlo + 2 * 32768), nullptr, hPtr);
    k_agg<<<agg_blocks, 512>>>(hPtr, b2, h2Ptr);
    // head
    k_gemm_mma<64><<<NT, 256, SMEM_64>>>(h2Ptr, (const uint4*)(whi + 3 * 32768),
                                         (const uint4*)(wlo + 3 * 32768), blin, out);
}

// round 15
// speedup vs baseline: 1.1382x; 1.0887x over previous
#include <cuda_runtime.h>
#include <cuda_bf16.h>
#include <cstdint>

#define NNODES 50000
#define NEDGES 640000
#define HID    128
#define CLS    64
#define NT     391            // ceil(50000/128) M-tiles

#define SCAN_BLK 1024
#define NSCANBLK ((NNODES + SCAN_BLK - 1) / SCAN_BLK)   // 49

typedef unsigned long long u64;

// ---------------- scratch (static __device__, no allocation) ----------------
__device__ float g_h[NNODES * HID];                        // fp32 hidden (ping)
__device__ float g_h2[NNODES * HID];                       // fp32 hidden (pong)
__device__ __align__(16) unsigned char g_Whi[3 * 32768 + 16384]; // W^T tiles
__device__ __align__(16) unsigned char g_Wlo[3 * 32768 + 16384];
__device__ float g_dinv[NNODES];
__device__ int   g_cnt[NNODES];      // zero-initialized; invariant restored by k_agg
__device__ int   g_rowptr[NNODES + 1];
__device__ int   g_pos[NNODES];
__device__ __align__(8) int2 g_edge[NEDGES];   // fused (srow, dinv-bits)

// ---------------- helpers ----------------
__device__ __forceinline__ uint32_t smem_to_u32(const void* p) {
    uint32_t a;
    asm("{ .reg .u64 t; cvta.to.shared.u64 t, %1; cvt.u32.u64 %0, t; }" : "=r"(a) : "l"(p));
    return a;
}

// tile layout: 128-bf16 rows (256B), 16B chunks XOR-swizzled by row
__device__ __forceinline__ uint32_t tile_off(int r, int k) {
    return (uint32_t)(r * 256 + 16 * (((k >> 3) ^ (r & 7))) + (k & 7) * 2);
}

__device__ __forceinline__ void ldsm4(uint32_t* r, uint32_t addr) {
    asm volatile("ldmatrix.sync.aligned.m8n8.x4.shared.b16 {%0,%1,%2,%3}, [%4];"
                 : "=r"(r[0]), "=r"(r[1]), "=r"(r[2]), "=r"(r[3]) : "r"(addr));
}
__device__ __forceinline__ void mma16816(float* c, const uint32_t* a, const uint32_t* b) {
    asm volatile("mma.sync.aligned.m16n8k16.row.col.f32.bf16.bf16.f32 "
                 "{%0,%1,%2,%3}, {%4,%5,%6,%7}, {%8,%9}, {%0,%1,%2,%3};"
                 : "+f"(c[0]), "+f"(c[1]), "+f"(c[2]), "+f"(c[3])
                 : "r"(a[0]), "r"(a[1]), "r"(a[2]), "r"(a[3]), "r"(b[0]), "r"(b[1]));
}

// split one float4 into hi/lo bf16x4 and store 8B each
__device__ __forceinline__ void split_store(char* hiB, char* loB, uint32_t off, float4 v) {
    __nv_bfloat162 h0 = __floats2bfloat162_rn(v.x, v.y);
    __nv_bfloat162 h1 = __floats2bfloat162_rn(v.z, v.w);
    float rx = v.x - __low2float(h0);
    float ry = v.y - __high2float(h0);
    float rz = v.z - __low2float(h1);
    float rw = v.w - __high2float(h1);
    __nv_bfloat162 l0 = __floats2bfloat162_rn(rx, ry);
    __nv_bfloat162 l1 = __floats2bfloat162_rn(rz, rw);
    uint2 hu = make_uint2(*(uint32_t*)&h0, *(uint32_t*)&h1);
    uint2 lu = make_uint2(*(uint32_t*)&l0, *(uint32_t*)&l1);
    *reinterpret_cast<uint2*>(hiB + off) = hu;
    *reinterpret_cast<uint2*>(loB + off) = lu;
}

// ---------------- preprocessing ----------------
__global__ void k_count(const int* __restrict__ col) {
    int e = blockIdx.x * blockDim.x + threadIdx.x;
    if (e < NEDGES) atomicAdd(&g_cnt[col[e]], 1);
}

// fused: per-block prefix base + dinv + scan -> rowptr/pos (g_cnt cleared in k_agg)
__global__ void k_scan_fused() {
    __shared__ int warp_sums[32];
    __shared__ int s_base;
    const int tid  = threadIdx.x;
    const int lane = tid & 31;
    const int wid  = tid >> 5;
    const int bid  = blockIdx.x;

    int pre = 0;
    const int lim = bid * SCAN_BLK;
    for (int j = tid; j < lim; j += SCAN_BLK) pre += g_cnt[j];
    #pragma unroll
    for (int o = 16; o > 0; o >>= 1) pre += __shfl_down_sync(0xffffffffu, pre, o);
    if (lane == 0) warp_sums[wid] = pre;
    __syncthreads();
    if (wid == 0) {
        int s = warp_sums[lane];
        #pragma unroll
        for (int o = 16; o > 0; o >>= 1) s += __shfl_down_sync(0xffffffffu, s, o);
        if (lane == 0) s_base = s;
    }
    __syncthreads();

    if (bid == 0 && tid == 0) g_rowptr[NNODES] = NEDGES;

    int i = bid * SCAN_BLK + tid;
    int v = 0;
    if (i < NNODES) {
        v = g_cnt[i];
        g_dinv[i] = rsqrtf((float)v + 1.0f);
    }
    int x = v;
    #pragma unroll
    for (int o = 1; o < 32; o <<= 1) {
        int y = __shfl_up_sync(0xffffffffu, x, o);
        if (lane >= o) x += y;
    }
    if (lane == 31) warp_sums[wid] = x;
    __syncthreads();
    if (wid == 0) {
        int s = warp_sums[lane];
        #pragma unroll
        for (int o = 1; o < 32; o <<= 1) {
            int y = __shfl_up_sync(0xffffffffu, s, o);
            if (lane >= o) s += y;
        }
        warp_sums[lane] = s;
    }
    __syncthreads();
    int excl = s_base + x - v + (wid > 0 ? warp_sums[wid - 1] : 0);
    if (i < NNODES) { g_rowptr[i] = excl; g_pos[i] = excl; }
}

__global__ void k_scatter(const int* __restrict__ row, const int* __restrict__ col) {
    int e = blockIdx.x * blockDim.x + threadIdx.x;
    if (e < NEDGES) {
        int c = col[e];
        int r = row[e];
        int p = atomicAdd(&g_pos[c], 1);
        g_edge[p] = make_int2(r, __float_as_int(g_dinv[r]));
    }
}

// ---------------- weight prep: W[K,N] -> W^T[N,K] tiles, hi/lo ----------------
__global__ void k_wprep(const float* __restrict__ W0, const float* __restrict__ W1,
                        const float* __restrict__ W2, const float* __restrict__ Wlin) {
    int idx = blockIdx.x * blockDim.x + threadIdx.x;
    if (idx >= 3 * 16384 + 8192) return;
    float w;
    uint32_t dst;
    if (idx < 3 * 16384) {
        int g = idx >> 14;
        int rem = idx & 16383;
        int k = rem >> 7;
        int n = rem & 127;
        const float* W = (g == 0) ? W0 : (g == 1) ? W1 : W2;
        w = W[k * 128 + n];
        dst = g * 32768 + tile_off(n, k);
    } else {
        int rem = idx - 3 * 16384;
        int k = rem >> 6;
        int n = rem & 63;
        w = Wlin[k * 64 + n];
        dst = 3 * 32768 + tile_off(n, k);
    }
    __nv_bfloat16 hi = __float2bfloat16_rn(w);
    float lo = w - __bfloat162float(hi);
    *reinterpret_cast<__nv_bfloat16*>(g_Whi + dst) = hi;
    *reinterpret_cast<__nv_bfloat16*>(g_Wlo + dst) = __float2bfloat16_rn(lo);
}

// ---------------- tensor-core GEMM via mma.sync, split-bf16 x3 passes ----------
// C[M, NCOLS] = A[M,128] @ W[128,NCOLS]; A fp32, split hi/lo into smem on load.
// 256 threads, warp tile 32 x NCOLS/2.
template <int NCOLS>
__global__ __launch_bounds__(256, 1)
void k_gemm_mma(const float* __restrict__ A,
                const uint4* __restrict__ Bhi4, const uint4* __restrict__ Blo4,
                const float* __restrict__ bias, float* __restrict__ C) {
    constexpr int A_BYTES = 32768;
    constexpr int B_BYTES = NCOLS * 256;
    constexpr int OFF_AHI = 0;
    constexpr int OFF_ALO = A_BYTES;
    constexpr int OFF_BHI = 2 * A_BYTES;
    constexpr int OFF_BLO = 2 * A_BYTES + B_BYTES;
    constexpr int NT8 = NCOLS / 16;
    extern __shared__ __align__(16) char smem[];

    const int tid  = threadIdx.x;
    const int wid  = tid >> 5;
    const int lane = tid & 31;
    const int tile = blockIdx.x;

    {
        char* hiB = smem + OFF_AHI;
        char* loB = smem + OFF_ALO;
        #pragma unroll
        for (int it = 0; it < 16; it++) {
            int idx = tid + it * 256;
            int r   = idx >> 5;
            int c4  = (idx & 31) * 4;
            int gr  = tile * 128 + r;
            float4 v = make_float4(0.f, 0.f, 0.f, 0.f);
            if (gr < NNODES)
                v = *reinterpret_cast<const float4*>(A + (size_t)gr * HID + c4);
            split_store(hiB, loB, tile_off(r, c4), v);
        }
        uint4* bH = reinterpret_cast<uint4*>(smem + OFF_BHI);
        uint4* bL = reinterpret_cast<uint4*>(smem + OFF_BLO);
        #pragma unroll
        for (int i = tid; i < B_BYTES / 16; i += 256) { bH[i] = Bhi4[i]; bL[i] = Blo4[i]; }
    }
    __syncthreads();

    const int wm  = wid >> 1;
    const int wn  = wid & 1;
    const int m0w = wm * 32;
    const int n0w = wn * (NCOLS / 2);

    float acc[2][NT8][4];
    #pragma unroll
    for (int mi = 0; mi < 2; mi++)
        #pragma unroll
        for (int ni = 0; ni < NT8; ni++)
            #pragma unroll
            for (int q = 0; q < 4; q++) acc[mi][ni][q] = 0.0f;

    const uint32_t sb = smem_to_u32(smem);
    const int arow    = m0w + (lane & 15);
    const int asw     = arow & 7;
    const int akc_add = lane >> 4;
    const int bn      = n0w + (lane & 7) + ((lane >> 4) << 3);
    const int bsw     = bn & 7;
    const int bkc_add = (lane >> 3) & 1;

    #pragma unroll
    for (int pass = 0; pass < 3; pass++) {
        const uint32_t Ab = sb + ((pass == 2) ? OFF_ALO : OFF_AHI);
        const uint32_t Bb = sb + ((pass == 1) ? OFF_BLO : OFF_BHI);
        #pragma unroll
        for (int s = 0; s < 8; s++) {
            const int kca = 2 * s + akc_add;
            const int kcb = 2 * s + bkc_add;
            uint32_t a[2][4];
            #pragma unroll
            for (int mi = 0; mi < 2; mi++)
                ldsm4(a[mi], Ab + (uint32_t)((arow + mi * 16) * 256 + 16 * (kca ^ asw)));
            uint32_t b[NT8][2];
            #pragma unroll
            for (int nj = 0; nj < NT8 / 2; nj++) {
                uint32_t r[4];
                ldsm4(r, Bb + (uint32_t)((bn + nj * 16) * 256 + 16 * (kcb ^ bsw)));
                b[2 * nj][0] = r[0]; b[2 * nj][1] = r[1];
                b[2 * nj + 1][0] = r[2]; b[2 * nj + 1][1] = r[3];
            }
            #pragma unroll
            for (int mi = 0; mi < 2; mi++)
                #pragma unroll
                for (int ni = 0; ni < NT8; ni++)
                    mma16816(acc[mi][ni], a[mi], b[ni]);
        }
    }

    const int rbase = tile * 128 + m0w;
    #pragma unroll
    for (int mi = 0; mi < 2; mi++) {
        int r0 = rbase + mi * 16 + (lane >> 2);
        int r1 = r0 + 8;
        #pragma unroll
        for (int ni = 0; ni < NT8; ni++) {
            int c = n0w + ni * 8 + (lane & 3) * 2;
            float bx = 0.f, by = 0.f;
            if (bias) { bx = bias[c]; by = bias[c + 1]; }
            if (r0 < NNODES) {
                float2 v = make_float2(acc[mi][ni][0] + bx, acc[mi][ni][1] + by);
                *reinterpret_cast<float2*>(C + (size_t)r0 * NCOLS + c) = v;
            }
            if (r1 < NNODES) {
                float2 v = make_float2(acc[mi][ni][2] + bx, acc[mi][ni][3] + by);
                *reinterpret_cast<float2*>(C + (size_t)r1 * NCOLS + c) = v;
            }
        }
    }
}

// ---------------- aggregation (4-way edge ILP): fp32 in, fp32 out ----------------
// also restores the g_cnt == 0 invariant for the next launch replay
__global__ void k_agg(const float* __restrict__ h,
                      const float* __restrict__ bias,
                      float* __restrict__ out) {
    int gwarp = (blockIdx.x * blockDim.x + threadIdx.x) >> 5;
    int lane  = threadIdx.x & 31;
    if (gwarp >= NNODES) return;
    const int n = gwarp;
    if (lane == 0) g_cnt[n] = 0;     // maintain zero-invariant (idempotent)

    const float dn = g_dinv[n];
    const size_t feat = (size_t)lane * 4;

    float4 self = *reinterpret_cast<const float4*>(h + (size_t)n * HID + feat);
    const float sn = dn * dn;
    float4 acc0 = make_float4(self.x * sn, self.y * sn, self.z * sn, self.w * sn);
    float4 acc1 = make_float4(0.f, 0.f, 0.f, 0.f);
    float4 acc2 = make_float4(0.f, 0.f, 0.f, 0.f);
    float4 acc3 = make_float4(0.f, 0.f, 0.f, 0.f);

    const int beg = g_rowptr[n];
    const int end = g_rowptr[n + 1];

    int e = beg;
    for (; e + 4 <= end; e += 4) {
        int2 e0 = g_edge[e],     e1 = g_edge[e + 1];
        int2 e2 = g_edge[e + 2], e3 = g_edge[e + 3];
        float w0 = __int_as_float(e0.y) * dn, w1 = __int_as_float(e1.y) * dn;
        float w2 = __int_as_float(e2.y) * dn, w3 = __int_as_float(e3.y) * dn;
        float4 v0 = *reinterpret_cast<const float4*>(h + (size_t)e0.x * HID + feat);
        float4 v1 = *reinterpret_cast<const float4*>(h + (size_t)e1.x * HID + feat);
        float4 v2 = *reinterpret_cast<const float4*>(h + (size_t)e2.x * HID + feat);
        float4 v3 = *reinterpret_cast<const float4*>(h + (size_t)e3.x * HID + feat);
        acc0.x += v0.x * w0; acc0.y += v0.y * w0; acc0.z += v0.z * w0; acc0.w += v0.w * w0;
        acc1.x += v1.x * w1; acc1.y += v1.y * w1; acc1.z += v1.z * w1; acc1.w += v1.w * w1;
        acc2.x += v2.x * w2; acc2.y += v2.y * w2; acc2.z += v2.z * w2; acc2.w += v2.w * w2;
        acc3.x += v3.x * w3; acc3.y += v3.y * w3; acc3.z += v3.z * w3; acc3.w += v3.w * w3;
    }
    for (; e < end; ++e) {
        int2 ed = g_edge[e];
        float w = __int_as_float(ed.y) * dn;
        float4 v = *reinterpret_cast<const float4*>(h + (size_t)ed.x * HID + feat);
        acc0.x += v.x * w; acc0.y += v.y * w; acc0.z += v.z * w; acc0.w += v.w * w;
    }

    float4 acc;
    acc.x = (acc0.x + acc1.x) + (acc2.x + acc3.x);
    acc.y = (acc0.y + acc1.y) + (acc2.y + acc3.y);
    acc.z = (acc0.z + acc1.z) + (acc2.z + acc3.z);
    acc.w = (acc0.w + acc1.w) + (acc2.w + acc3.w);

    float4 b = *reinterpret_cast<const float4*>(bias + feat);
    acc.x = fmaxf(acc.x + b.x, 0.0f);
    acc.y = fmaxf(acc.y + b.y, 0.0f);
    acc.z = fmaxf(acc.z + b.z, 0.0f);
    acc.w = fmaxf(acc.w + b.w, 0.0f);

    *reinterpret_cast<float4*>(out + (size_t)n * HID + feat) = acc;
}

// ---------------- launch ----------------
extern "C" void kernel_launch(void* const* d_in, const int* in_sizes, int n_in,
                              void* d_out, int out_size) {
    const float* x    = (const float*)d_in[0];
    const int*   ei   = (const int*)d_in[1];
    const int*   row  = ei;
    const int*   col  = ei + NEDGES;
    const float* W0   = (const float*)d_in[2];
    const float* b0   = (const float*)d_in[3];
    const float* W1   = (const float*)d_in[4];
    const float* b1   = (const float*)d_in[5];
    const float* W2   = (const float*)d_in[6];
    const float* b2   = (const float*)d_in[7];
    const float* Wlin = (const float*)d_in[8];
    const float* blin = (const float*)d_in[9];
    float* out = (float*)d_out;

    float *hPtr, *h2Ptr;
    cudaGetSymbolAddress((void**)&hPtr, g_h);
    cudaGetSymbolAddress((void**)&h2Ptr, g_h2);
    unsigned char *whi, *wlo;
    cudaGetSymbolAddress((void**)&whi, g_Whi);
    cudaGetSymbolAddress((void**)&wlo, g_Wlo);

    constexpr int SMEM_128 = 2 * 32768 + 2 * 32768;  // 131072
    constexpr int SMEM_64  = 2 * 32768 + 2 * 16384;  //  98304
    cudaFuncSetAttribute(k_gemm_mma<128>, cudaFuncAttributeMaxDynamicSharedMemorySize, SMEM_128);
    cudaFuncSetAttribute(k_gemm_mma<64>,  cudaFuncAttributeMaxDynamicSharedMemorySize, SMEM_64);

    // one-time side-stream + events (handles only; no device memory)
    static cudaStream_t s2 = nullptr;
    static cudaEvent_t evFork = nullptr, evJoin = nullptr;
    if (s2 == nullptr) {
        cudaStreamCreateWithFlags(&s2, cudaStreamNonBlocking);
        cudaEventCreateWithFlags(&evFork, cudaEventDisableTiming);
        cudaEventCreateWithFlags(&evJoin, cudaEventDisableTiming);
    }

    // fork: weight prep + layer-0 GEMM (independent of graph) on s2
    cudaEventRecord(evFork, 0);
    cudaStreamWaitEvent(s2, evFork, 0);
    k_wprep<<<(3 * 16384 + 8192 + 255) / 256, 256, 0, s2>>>(W0, W1, W2, Wlin);
    k_gemm_mma<128><<<NT, 256, SMEM_128, s2>>>(x, (const uint4*)(whi + 0 * 32768),
                                               (const uint4*)(wlo + 0 * 32768), nullptr, hPtr);
    cudaEventRecord(evJoin, s2);

    // main stream: graph preprocessing (g_cnt zero-invariant restored by k_agg)
    k_count<<<(NEDGES + 255) / 256, 256>>>(col);
    k_scan_fused<<<NSCANBLK, SCAN_BLK>>>();
    k_scatter<<<(NEDGES + 255) / 256, 256>>>(row, col);

    // join
    cudaStreamWaitEvent(0, evJoin, 0);

    const int agg_blocks = (NNODES * 32 + 255) / 256;

    k_agg<<<agg_blocks, 256>>>(hPtr, b0, h2Ptr);
    // layer 1
    k_gemm_mma<128><<<NT, 256, SMEM_128>>>(h2Ptr, (const uint4*)(whi + 1 * 32768),
                                           (const uint4*)(wlo + 1 * 32768), nullptr, hPtr);
    k_agg<<<agg_blocks, 256>>>(hPtr, b1, h2Ptr);
    // layer 2
    k_gemm_mma<128><<<NT, 256, SMEM_128>>>(h2Ptr, (const uint4*)(whi + 2 * 32768),
                                           (const uint4*)(wlo + 2 * 32768), nullptr, hPtr);
    k_agg<<<agg_blocks, 256>>>(hPtr, b2, h2Ptr);
    // head
    k_gemm_mma<64><<<NT, 256, SMEM_64>>>(h2Ptr, (const uint4*)(whi + 3 * 32768),
                                         (const uint4*)(wlo + 3 * 32768), blin, out);
}

// round 16
// speedup vs baseline: 1.1854x; 1.0415x over previous
#include <cuda_runtime.h>
#include <cuda_bf16.h>
#include <cstdint>

#define NNODES 50000
#define NEDGES 640000
#define HID    128
#define CLS    64
#define NT     391            // ceil(50000/128) M-tiles

#define SCAN_BLK 1024
#define NSCANBLK ((NNODES + SCAN_BLK - 1) / SCAN_BLK)   // 49

typedef unsigned long long u64;

// ---------------- scratch (static __device__, no allocation) ----------------
__device__ float g_h[NNODES * HID];                        // z' = z*dinv (GEMM out)
__device__ float g_h2[NNODES * HID];                       // h (agg out)
__device__ __align__(16) unsigned char g_Whi[3 * 32768 + 16384]; // W^T tiles
__device__ __align__(16) unsigned char g_Wlo[3 * 32768 + 16384];
__device__ float g_dinv[NNODES];
__device__ __align__(16) int g_cnt[NNODES];  // zero at launch start; restored by k_agg
__device__ int   g_rowptr[NNODES + 1];
__device__ int   g_pos[NNODES];
__device__ int   g_srow[NEDGES];             // edge source only (4B/edge)

// ---------------- helpers ----------------
__device__ __forceinline__ uint32_t smem_to_u32(const void* p) {
    uint32_t a;
    asm("{ .reg .u64 t; cvta.to.shared.u64 t, %1; cvt.u32.u64 %0, t; }" : "=r"(a) : "l"(p));
    return a;
}

// tile layout: 128-bf16 rows (256B), 16B chunks XOR-swizzled by row
__device__ __forceinline__ uint32_t tile_off(int r, int k) {
    return (uint32_t)(r * 256 + 16 * (((k >> 3) ^ (r & 7))) + (k & 7) * 2);
}

__device__ __forceinline__ void ldsm4(uint32_t* r, uint32_t addr) {
    asm volatile("ldmatrix.sync.aligned.m8n8.x4.shared.b16 {%0,%1,%2,%3}, [%4];"
                 : "=r"(r[0]), "=r"(r[1]), "=r"(r[2]), "=r"(r[3]) : "r"(addr));
}
__device__ __forceinline__ void mma16816(float* c, const uint32_t* a, const uint32_t* b) {
    asm volatile("mma.sync.aligned.m16n8k16.row.col.f32.bf16.bf16.f32 "
                 "{%0,%1,%2,%3}, {%4,%5,%6,%7}, {%8,%9}, {%0,%1,%2,%3};"
                 : "+f"(c[0]), "+f"(c[1]), "+f"(c[2]), "+f"(c[3])
                 : "r"(a[0]), "r"(a[1]), "r"(a[2]), "r"(a[3]), "r"(b[0]), "r"(b[1]));
}

// split one float4 into hi/lo bf16x4 and store 8B each
__device__ __forceinline__ void split_store(char* hiB, char* loB, uint32_t off, float4 v) {
    __nv_bfloat162 h0 = __floats2bfloat162_rn(v.x, v.y);
    __nv_bfloat162 h1 = __floats2bfloat162_rn(v.z, v.w);
    float rx = v.x - __low2float(h0);
    float ry = v.y - __high2float(h0);
    float rz = v.z - __low2float(h1);
    float rw = v.w - __high2float(h1);
    __nv_bfloat162 l0 = __floats2bfloat162_rn(rx, ry);
    __nv_bfloat162 l1 = __floats2bfloat162_rn(rz, rw);
    uint2 hu = make_uint2(*(uint32_t*)&h0, *(uint32_t*)&h1);
    uint2 lu = make_uint2(*(uint32_t*)&l0, *(uint32_t*)&l1);
    *reinterpret_cast<uint2*>(hiB + off) = hu;
    *reinterpret_cast<uint2*>(loB + off) = lu;
}

// ---------------- preprocessing ----------------
__global__ void k_count(const int* __restrict__ col) {
    int e = blockIdx.x * blockDim.x + threadIdx.x;
    if (e < NEDGES) atomicAdd(&g_cnt[col[e]], 1);
}

// fused: per-block prefix base (int4-vectorized) + dinv + scan -> rowptr/pos
__global__ void k_scan_fused() {
    __shared__ int warp_sums[32];
    __shared__ int s_base;
    const int tid  = threadIdx.x;
    const int lane = tid & 31;
    const int wid  = tid >> 5;
    const int bid  = blockIdx.x;

    // phase A: s_base = sum(g_cnt[0 .. bid*SCAN_BLK)) via int4 loads
    int pre = 0;
    const int lim4 = bid * (SCAN_BLK / 4);          // int4 count (SCAN_BLK multiple of 4)
    const int4* cnt4 = reinterpret_cast<const int4*>(g_cnt);
    for (int j = tid; j < lim4; j += SCAN_BLK) {
        int4 v4 = cnt4[j];
        pre += (v4.x + v4.y) + (v4.z + v4.w);
    }
    #pragma unroll
    for (int o = 16; o > 0; o >>= 1) pre += __shfl_down_sync(0xffffffffu, pre, o);
    if (lane == 0) warp_sums[wid] = pre;
    __syncthreads();
    if (wid == 0) {
        int s = warp_sums[lane];
        #pragma unroll
        for (int o = 16; o > 0; o >>= 1) s += __shfl_down_sync(0xffffffffu, s, o);
        if (lane == 0) s_base = s;
    }
    __syncthreads();

    if (bid == 0 && tid == 0) g_rowptr[NNODES] = NEDGES;

    // phase B: dinv + per-block exclusive scan
    int i = bid * SCAN_BLK + tid;
    int v = 0;
    if (i < NNODES) {
        v = g_cnt[i];
        g_dinv[i] = rsqrtf((float)v + 1.0f);
    }
    int x = v;
    #pragma unroll
    for (int o = 1; o < 32; o <<= 1) {
        int y = __shfl_up_sync(0xffffffffu, x, o);
        if (lane >= o) x += y;
    }
    if (lane == 31) warp_sums[wid] = x;
    __syncthreads();
    if (wid == 0) {
        int s = warp_sums[lane];
        #pragma unroll
        for (int o = 1; o < 32; o <<= 1) {
            int y = __shfl_up_sync(0xffffffffu, s, o);
            if (lane >= o) s += y;
        }
        warp_sums[lane] = s;
    }
    __syncthreads();
    int excl = s_base + x - v + (wid > 0 ? warp_sums[wid - 1] : 0);
    if (i < NNODES) { g_rowptr[i] = excl; g_pos[i] = excl; }
}

__global__ void k_scatter(const int* __restrict__ row, const int* __restrict__ col) {
    int e = blockIdx.x * blockDim.x + threadIdx.x;
    if (e < NEDGES) {
        int c = col[e];
        int p = atomicAdd(&g_pos[c], 1);
        g_srow[p] = row[e];
    }
}

// ---------------- weight prep: W[K,N] -> W^T[N,K] tiles, hi/lo ----------------
__global__ void k_wprep(const float* __restrict__ W0, const float* __restrict__ W1,
                        const float* __restrict__ W2, const float* __restrict__ Wlin) {
    int idx = blockIdx.x * blockDim.x + threadIdx.x;
    if (idx >= 3 * 16384 + 8192) return;
    float w;
    uint32_t dst;
    if (idx < 3 * 16384) {
        int g = idx >> 14;
        int rem = idx & 16383;
        int k = rem >> 7;
        int n = rem & 127;
        const float* W = (g == 0) ? W0 : (g == 1) ? W1 : W2;
        w = W[k * 128 + n];
        dst = g * 32768 + tile_off(n, k);
    } else {
        int rem = idx - 3 * 16384;
        int k = rem >> 6;
        int n = rem & 63;
        w = Wlin[k * 64 + n];
        dst = 3 * 32768 + tile_off(n, k);
    }
    __nv_bfloat16 hi = __float2bfloat16_rn(w);
    float lo = w - __bfloat162float(hi);
    *reinterpret_cast<__nv_bfloat16*>(g_Whi + dst) = hi;
    *reinterpret_cast<__nv_bfloat16*>(g_Wlo + dst) = __float2bfloat16_rn(lo);
}

// ---------------- tensor-core GEMM via mma.sync, split-bf16 x3 passes ----------
// C[M, NCOLS] = (A[M,128] @ W[128,NCOLS] + bias) * (scaleRow ? scaleRow[m] : 1)
template <int NCOLS>
__global__ __launch_bounds__(256, 1)
void k_gemm_mma(const float* __restrict__ A,
                const uint4* __restrict__ Bhi4, const uint4* __restrict__ Blo4,
                const float* __restrict__ bias, float* __restrict__ C,
                const float* __restrict__ scaleRow) {
    constexpr int A_BYTES = 32768;
    constexpr int B_BYTES = NCOLS * 256;
    constexpr int OFF_AHI = 0;
    constexpr int OFF_ALO = A_BYTES;
    constexpr int OFF_BHI = 2 * A_BYTES;
    constexpr int OFF_BLO = 2 * A_BYTES + B_BYTES;
    constexpr int NT8 = NCOLS / 16;
    extern __shared__ __align__(16) char smem[];

    const int tid  = threadIdx.x;
    const int wid  = tid >> 5;
    const int lane = tid & 31;
    const int tile = blockIdx.x;

    {
        char* hiB = smem + OFF_AHI;
        char* loB = smem + OFF_ALO;
        #pragma unroll
        for (int it = 0; it < 16; it++) {
            int idx = tid + it * 256;
            int r   = idx >> 5;
            int c4  = (idx & 31) * 4;
            int gr  = tile * 128 + r;
            float4 v = make_float4(0.f, 0.f, 0.f, 0.f);
            if (gr < NNODES)
                v = *reinterpret_cast<const float4*>(A + (size_t)gr * HID + c4);
            split_store(hiB, loB, tile_off(r, c4), v);
        }
        uint4* bH = reinterpret_cast<uint4*>(smem + OFF_BHI);
        uint4* bL = reinterpret_cast<uint4*>(smem + OFF_BLO);
        #pragma unroll
        for (int i = tid; i < B_BYTES / 16; i += 256) { bH[i] = Bhi4[i]; bL[i] = Blo4[i]; }
    }
    __syncthreads();

    const int wm  = wid >> 1;
    const int wn  = wid & 1;
    const int m0w = wm * 32;
    const int n0w = wn * (NCOLS / 2);

    float acc[2][NT8][4];
    #pragma unroll
    for (int mi = 0; mi < 2; mi++)
        #pragma unroll
        for (int ni = 0; ni < NT8; ni++)
            #pragma unroll
            for (int q = 0; q < 4; q++) acc[mi][ni][q] = 0.0f;

    const uint32_t sb = smem_to_u32(smem);
    const int arow    = m0w + (lane & 15);
    const int asw     = arow & 7;
    const int akc_add = lane >> 4;
    const int bn      = n0w + (lane & 7) + ((lane >> 4) << 3);
    const int bsw     = bn & 7;
    const int bkc_add = (lane >> 3) & 1;

    #pragma unroll
    for (int pass = 0; pass < 3; pass++) {
        const uint32_t Ab = sb + ((pass == 2) ? OFF_ALO : OFF_AHI);
        const uint32_t Bb = sb + ((pass == 1) ? OFF_BLO : OFF_BHI);
        #pragma unroll
        for (int s = 0; s < 8; s++) {
            const int kca = 2 * s + akc_add;
            const int kcb = 2 * s + bkc_add;
            uint32_t a[2][4];
            #pragma unroll
            for (int mi = 0; mi < 2; mi++)
                ldsm4(a[mi], Ab + (uint32_t)((arow + mi * 16) * 256 + 16 * (kca ^ asw)));
            uint32_t b[NT8][2];
            #pragma unroll
            for (int nj = 0; nj < NT8 / 2; nj++) {
                uint32_t r[4];
                ldsm4(r, Bb + (uint32_t)((bn + nj * 16) * 256 + 16 * (kcb ^ bsw)));
                b[2 * nj][0] = r[0]; b[2 * nj][1] = r[1];
                b[2 * nj + 1][0] = r[2]; b[2 * nj + 1][1] = r[3];
            }
            #pragma unroll
            for (int mi = 0; mi < 2; mi++)
                #pragma unroll
                for (int ni = 0; ni < NT8; ni++)
                    mma16816(acc[mi][ni], a[mi], b[ni]);
        }
    }

    const int rbase = tile * 128 + m0w;
    #pragma unroll
    for (int mi = 0; mi < 2; mi++) {
        int r0 = rbase + mi * 16 + (lane >> 2);
        int r1 = r0 + 8;
        float s0 = 1.0f, s1 = 1.0f;
        if (scaleRow) {
            if (r0 < NNODES) s0 = scaleRow[r0];
            if (r1 < NNODES) s1 = scaleRow[r1];
        }
        #pragma unroll
        for (int ni = 0; ni < NT8; ni++) {
            int c = n0w + ni * 8 + (lane & 3) * 2;
            float bx = 0.f, by = 0.f;
            if (bias) { bx = bias[c]; by = bias[c + 1]; }
            if (r0 < NNODES) {
                float2 v = make_float2((acc[mi][ni][0] + bx) * s0,
                                       (acc[mi][ni][1] + by) * s0);
                *reinterpret_cast<float2*>(C + (size_t)r0 * NCOLS + c) = v;
            }
            if (r1 < NNODES) {
                float2 v = make_float2((acc[mi][ni][2] + bx) * s1,
                                       (acc[mi][ni][3] + by) * s1);
                *reinterpret_cast<float2*>(C + (size_t)r1 * NCOLS + c) = v;
            }
        }
    }
}

// ---------------- aggregation (4-way edge ILP): unweighted gather of z' -------
// in: zp = z*dinv. out(n) = relu(dn * (sum_e zp[src] + zp[n]) + bias)
// also restores the g_cnt == 0 invariant for the next launch replay
__global__ void k_agg(const float* __restrict__ zp,
                      const float* __restrict__ bias,
                      float* __restrict__ out) {
    int gwarp = (blockIdx.x * blockDim.x + threadIdx.x) >> 5;
    int lane  = threadIdx.x & 31;
    if (gwarp >= NNODES) return;
    const int n = gwarp;
    if (lane == 0) g_cnt[n] = 0;     // maintain zero-invariant (idempotent)

    const float dn = g_dinv[n];
    const size_t feat = (size_t)lane * 4;

    float4 acc0 = *reinterpret_cast<const float4*>(zp + (size_t)n * HID + feat); // self
    float4 acc1 = make_float4(0.f, 0.f, 0.f, 0.f);
    float4 acc2 = make_float4(0.f, 0.f, 0.f, 0.f);
    float4 acc3 = make_float4(0.f, 0.f, 0.f, 0.f);

    const int beg = g_rowptr[n];
    const int end = g_rowptr[n + 1];

    int e = beg;
    for (; e + 4 <= end; e += 4) {
        int r0 = g_srow[e],     r1 = g_srow[e + 1];
        int r2 = g_srow[e + 2], r3 = g_srow[e + 3];
        float4 v0 = *reinterpret_cast<const float4*>(zp + (size_t)r0 * HID + feat);
        float4 v1 = *reinterpret_cast<const float4*>(zp + (size_t)r1 * HID + feat);
        float4 v2 = *reinterpret_cast<const float4*>(zp + (size_t)r2 * HID + feat);
        float4 v3 = *reinterpret_cast<const float4*>(zp + (size_t)r3 * HID + feat);
        acc0.x += v0.x; acc0.y += v0.y; acc0.z += v0.z; acc0.w += v0.w;
        acc1.x += v1.x; acc1.y += v1.y; acc1.z += v1.z; acc1.w += v1.w;
        acc2.x += v2.x; acc2.y += v2.y; acc2.z += v2.z; acc2.w += v2.w;
        acc3.x += v3.x; acc3.y += v3.y; acc3.z += v3.z; acc3.w += v3.w;
    }
    for (; e < end; ++e) {
        int r = g_srow[e];
        float4 v = *reinterpret_cast<const float4*>(zp + (size_t)r * HID + feat);
        acc0.x += v.x; acc0.y += v.y; acc0.z += v.z; acc0.w += v.w;
    }

    float4 acc;
    acc.x = (acc0.x + acc1.x) + (acc2.x + acc3.x);
    acc.y = (acc0.y + acc1.y) + (acc2.y + acc3.y);
    acc.z = (acc0.z + acc1.z) + (acc2.z + acc3.z);
    acc.w = (acc0.w + acc1.w) + (acc2.w + acc3.w);

    float4 b = *reinterpret_cast<const float4*>(bias + feat);
    acc.x = fmaxf(fmaf(acc.x, dn, b.x), 0.0f);
    acc.y = fmaxf(fmaf(acc.y, dn, b.y), 0.0f);
    acc.z = fmaxf(fmaf(acc.z, dn, b.z), 0.0f);
    acc.w = fmaxf(fmaf(acc.w, dn, b.w), 0.0f);

    *reinterpret_cast<float4*>(out + (size_t)n * HID + feat) = acc;
}

// ---------------- launch ----------------
extern "C" void kernel_launch(void* const* d_in, const int* in_sizes, int n_in,
                              void* d_out, int out_size) {
    const float* x    = (const float*)d_in[0];
    const int*   ei   = (const int*)d_in[1];
    const int*   row  = ei;
    const int*   col  = ei + NEDGES;
    const float* W0   = (const float*)d_in[2];
    const float* b0   = (const float*)d_in[3];
    const float* W1   = (const float*)d_in[4];
    const float* b1   = (const float*)d_in[5];
    const float* W2   = (const float*)d_in[6];
    const float* b2   = (const float*)d_in[7];
    const float* Wlin = (const float*)d_in[8];
    const float* blin = (const float*)d_in[9];
    float* out = (float*)d_out;

    float *hPtr, *h2Ptr, *dinvPtr;
    cudaGetSymbolAddress((void**)&hPtr, g_h);
    cudaGetSymbolAddress((void**)&h2Ptr, g_h2);
    cudaGetSymbolAddress((void**)&dinvPtr, g_dinv);
    unsigned char *whi, *wlo;
    cudaGetSymbolAddress((void**)&whi, g_Whi);
    cudaGetSymbolAddress((void**)&wlo, g_Wlo);

    constexpr int SMEM_128 = 2 * 32768 + 2 * 32768;  // 131072
    constexpr int SMEM_64  = 2 * 32768 + 2 * 16384;  //  98304
    cudaFuncSetAttribute(k_gemm_mma<128>, cudaFuncAttributeMaxDynamicSharedMemorySize, SMEM_128);
    cudaFuncSetAttribute(k_gemm_mma<64>,  cudaFuncAttributeMaxDynamicSharedMemorySize, SMEM_64);

    // one-time side-stream + events (handles only; no device memory)
    static cudaStream_t s2 = nullptr;
    static cudaEvent_t evFork = nullptr, evScan = nullptr, evJoin = nullptr;
    if (s2 == nullptr) {
        cudaStreamCreateWithFlags(&s2, cudaStreamNonBlocking);
        cudaEventCreateWithFlags(&evFork, cudaEventDisableTiming);
        cudaEventCreateWithFlags(&evScan, cudaEventDisableTiming);
        cudaEventCreateWithFlags(&evJoin, cudaEventDisableTiming);
    }

    // fork: weight prep on s2 (fully independent)
    cudaEventRecord(evFork, 0);
    cudaStreamWaitEvent(s2, evFork, 0);
    k_wprep<<<(3 * 16384 + 8192 + 255) / 256, 256, 0, s2>>>(W0, W1, W2, Wlin);

    // main stream: count + scan (produces dinv, rowptr, pos)
    k_count<<<(NEDGES + 255) / 256, 256>>>(col);
    k_scan_fused<<<NSCANBLK, SCAN_BLK>>>();
    cudaEventRecord(evScan, 0);

    // s2: layer-0 GEMM (needs x, weights, dinv) overlaps with scatter on main
    cudaStreamWaitEvent(s2, evScan, 0);
    k_gemm_mma<128><<<NT, 256, SMEM_128, s2>>>(x, (const uint4*)(whi + 0 * 32768),
                                               (const uint4*)(wlo + 0 * 32768),
                                               nullptr, hPtr, dinvPtr);
    cudaEventRecord(evJoin, s2);

    // main: scatter (needs pos from scan)
    k_scatter<<<(NEDGES + 255) / 256, 256>>>(row, col);

    // join
    cudaStreamWaitEvent(0, evJoin, 0);

    const int agg_blocks = (NNODES * 32 + 255) / 256;

    // layer boundaries: agg(z') -> h ; gemm(h)*dinv -> z'
    k_agg<<<agg_blocks, 256>>>(hPtr, b0, h2Ptr);
    k_gemm_mma<128><<<NT, 256, SMEM_128>>>(h2Ptr, (const uint4*)(whi + 1 * 32768),
                                           (const uint4*)(wlo + 1 * 32768),
                                           nullptr, hPtr, dinvPtr);
    k_agg<<<agg_blocks, 256>>>(hPtr, b1, h2Ptr);
    k_gemm_mma<128><<<NT, 256, SMEM_128>>>(h2Ptr, (const uint4*)(whi + 2 * 32768),
                                           (const uint4*)(wlo + 2 * 32768),
                                           nullptr, hPtr, dinvPtr);
    k_agg<<<agg_blocks, 256>>>(hPtr, b2, h2Ptr);
    // head: no row scaling, +bias
    k_gemm_mma<64><<<NT, 256, SMEM_64>>>(h2Ptr, (const uint4*)(whi + 3 * 32768),
                                         (const uint4*)(wlo + 3 * 32768),
                                         blin, out, nullptr);
}